// round 1
// baseline (speedup 1.0000x reference)
#include <cuda_runtime.h>
#include <cstdint>

#define Bq 32
#define Nn 64
#define Hh 128
#define Cc 16
#define SIGMA 0.5f
#define CHUNK 4
#define PAD 68

// ---------------- device scratch (no allocation allowed) ----------------
__device__ float g_Anorm[Bq * Nn * Nn];
__device__ float g_xe[Bq * Nn * Hh];
__device__ unsigned long long g_adjbits[Bq * Nn];
__device__ unsigned long long g_maskbits[Bq];
__device__ int g_maxcl[Bq];

// ---------------- kernel 0: zero accumulators ----------------
__global__ void zero_kernel(float* out, int n) {
    for (int i = blockIdx.x * blockDim.x + threadIdx.x; i < n;
         i += gridDim.x * blockDim.x)
        out[i] = 0.f;
    if (blockIdx.x == 0 && threadIdx.x < Bq) g_maxcl[threadIdx.x] = 0;
}

// ---------------- kernel 1: per-batch precompute --------------
// Anorm (GCN-normalized adjacency with diag=1), raw adjacency bitmasks,
// mask bitmask (with runtime dtype detection: bool / int32 / float32).
__global__ void prep_kernel(const float* __restrict__ adj, const void* maskp) {
    int b = blockIdx.x;
    int i = threadIdx.x;  // 64 threads
    __shared__ float deg[Nn];

    if (i == 0) {
        unsigned first = ((const unsigned*)maskp)[0];
        int mode = (first == 1u) ? 1 : ((first == 0x3F800000u) ? 2 : 0);
        unsigned long long bits = 0;
        for (int j = 0; j < Nn; j++) {
            bool m;
            if (mode == 0)      m = ((const unsigned char*)maskp)[b * Nn + j] != 0;
            else if (mode == 1) m = ((const int*)maskp)[b * Nn + j] != 0;
            else                m = ((const float*)maskp)[b * Nn + j] != 0.f;
            if (m) bits |= 1ull << j;
        }
        g_maskbits[b] = bits;
    }

    float s = 0.f;
    unsigned long long abits = 0;
    const float* arow = adj + (size_t)b * Nn * Nn + (size_t)i * Nn;
    for (int j = 0; j < Nn; j++) {
        float v = arow[j];
        if (v > 0.f) abits |= 1ull << j;
        s += (j == i) ? 1.f : v;
    }
    g_adjbits[b * Nn + i] = abits;
    deg[i] = rsqrtf(fmaxf(s, 1.f));
    __syncthreads();
    float di = deg[i];
    float* onorm = g_Anorm + (size_t)b * Nn * Nn + (size_t)i * Nn;
    for (int j = 0; j < Nn; j++) {
        float a = (j == i) ? 1.f : arow[j];
        onorm[j] = di * a * deg[j];
    }
}

// ---------------- kernel 2: one GCN layer --------------------
// out = relu(Anorm @ (xin @ W) + bias) * mask     (per batch block)
// mode 0: xin = param, out = g_xe.   mode 1: xin = g_xe, out = param.
__global__ void gcn_layer(const float* __restrict__ xin_p,
                          const float* __restrict__ W,
                          const float* __restrict__ bias,
                          float* __restrict__ out_p, int mode) {
    int b = blockIdx.x;
    __shared__ float sh[Nn * Hh];  // 32KB
    const float* xin = (mode == 0) ? xin_p : (const float*)g_xe;
    float* out = (mode == 0) ? (float*)g_xe : out_p;

    int ho = threadIdx.x & 127;
    int half = threadIdx.x >> 7;  // 256 threads
    for (int i = half * 32; i < half * 32 + 32; i++) {
        float acc = 0.f;
        const float* xr = xin + ((size_t)b * Nn + i) * Hh;
        for (int k = 0; k < Hh; k++) acc += xr[k] * W[k * Hh + ho];
        sh[i * Hh + ho] = acc;
    }
    __syncthreads();
    unsigned long long mb = g_maskbits[b];
    float bv = bias[ho];
    for (int i = half * 32; i < half * 32 + 32; i++) {
        float acc = bv;
        const float* ar = g_Anorm + (size_t)b * Nn * Nn + (size_t)i * Nn;
        for (int j = 0; j < Nn; j++) acc += ar[j] * sh[j * Hh + ho];
        float v = ((mb >> i) & 1ull) ? fmaxf(acc, 0.f) : 0.f;
        out[((size_t)b * Nn + i) * Hh + ho] = v;
    }
}

// ---------------- kernel 3: main perturbed clustering ----------
struct SmemK5 {
    float xa[Hh * PAD];   // x_all transposed [h][node]
    float tt[Hh * PAD];   // relu(x@cW1+cb1) transposed [h][node]
    float xnew[Nn * Hh];  // per-chunk cluster sums
    float adjc[Nn * Nn];  // per-chunk cluster-adjacency counts
    float cw2[Hh * Cc];
    float lg[Nn * Cc];
    unsigned long long adjraw[Nn];
    unsigned long long reach[Nn];
    unsigned long long nodemask[Nn];
    unsigned long long rowOr[Nn];
    unsigned long long present;
    int concepts[Nn];
    int assign[Nn];
    int ncl;
};

__global__ void main_kernel(const float* __restrict__ xemb,
                            const float* __restrict__ noise,
                            const float* __restrict__ cW1,
                            const float* __restrict__ cb1,
                            const float* __restrict__ cW2,
                            const float* __restrict__ cb2,
                            float* __restrict__ outXnew,
                            float* __restrict__ outAdj,
                            float* __restrict__ outAssign,
                            int S, float invS) {
    extern __shared__ char smemraw[];
    SmemK5* sm = (SmemK5*)smemraw;
    int tid = threadIdx.x;  // 256
    int b = blockIdx.x % Bq;
    int chunk = blockIdx.x / Bq;

    for (int idx = tid; idx < Nn * Hh; idx += 256) sm->xnew[idx] = 0.f;
    for (int idx = tid; idx < Nn * Nn; idx += 256) sm->adjc[idx] = 0.f;
    for (int idx = tid; idx < Hh * Cc; idx += 256) sm->cw2[idx] = cW2[idx];
    if (tid < Nn) sm->adjraw[tid] = g_adjbits[b * Nn + tid];
    unsigned long long mb = g_maskbits[b];
    __syncthreads();

    int ho = tid & 127;
    int half = tid >> 7;
    float cb1v = cb1[ho];

    for (int sl = 0; sl < CHUNK; sl++) {
        int s = chunk * CHUNK + sl;
        if (s >= S) break;
        int bs = s * Bq + b;

        // ---- load x_all = x_emb + sigma*noise, transposed ----
        const float* xb = xemb + (size_t)b * Nn * Hh;
        const float* nz = noise + (size_t)bs * Nn * Hh;
        for (int idx = tid; idx < Nn * Hh; idx += 256) {
            int i = idx >> 7, h = idx & 127;
            sm->xa[h * PAD + i] = xb[idx] + SIGMA * nz[idx];
        }
        __syncthreads();

        // ---- t = relu(x_all @ cW1 + cb1), stored transposed ----
        for (int g = 0; g < 2; g++) {
            int r0 = half * 32 + g * 16;
            float acc[16];
#pragma unroll
            for (int ii = 0; ii < 16; ii++) acc[ii] = cb1v;
            for (int k = 0; k < Hh; k++) {
                float w = cW1[k * Hh + ho];
                const float4* xr = (const float4*)(sm->xa + k * PAD + r0);
#pragma unroll
                for (int q = 0; q < 4; q++) {
                    float4 v = xr[q];
                    acc[q * 4 + 0] += v.x * w;
                    acc[q * 4 + 1] += v.y * w;
                    acc[q * 4 + 2] += v.z * w;
                    acc[q * 4 + 3] += v.w * w;
                }
            }
            float4* to = (float4*)(sm->tt + ho * PAD + r0);
#pragma unroll
            for (int q = 0; q < 4; q++) {
                float4 v;
                v.x = fmaxf(acc[q * 4 + 0], 0.f);
                v.y = fmaxf(acc[q * 4 + 1], 0.f);
                v.z = fmaxf(acc[q * 4 + 2], 0.f);
                v.w = fmaxf(acc[q * 4 + 3], 0.f);
                to[q] = v;
            }
        }
        __syncthreads();

        // ---- logits = t @ cW2 + cb2 ----
        {
            int i = tid & 63, cg = tid >> 6;  // 4 cols per thread
            float a0 = cb2[cg * 4 + 0], a1 = cb2[cg * 4 + 1];
            float a2 = cb2[cg * 4 + 2], a3 = cb2[cg * 4 + 3];
            for (int k = 0; k < Hh; k++) {
                float tv = sm->tt[k * PAD + i];
                a0 += tv * sm->cw2[k * Cc + cg * 4 + 0];
                a1 += tv * sm->cw2[k * Cc + cg * 4 + 1];
                a2 += tv * sm->cw2[k * Cc + cg * 4 + 2];
                a3 += tv * sm->cw2[k * Cc + cg * 4 + 3];
            }
            sm->lg[i * Cc + cg * 4 + 0] = a0;
            sm->lg[i * Cc + cg * 4 + 1] = a1;
            sm->lg[i * Cc + cg * 4 + 2] = a2;
            sm->lg[i * Cc + cg * 4 + 3] = a3;
        }
        __syncthreads();

        // ---- argmax (first max, like jnp.argmax) ----
        if (tid < Nn) {
            float best = sm->lg[tid * Cc];
            int bi = 0;
            for (int c = 1; c < Cc; c++) {
                float v = sm->lg[tid * Cc + c];
                if (v > best) { best = v; bi = c; }
            }
            sm->concepts[tid] = bi;
        }
        __syncthreads();

        // ---- edges (same concept & masked) + reach init ----
        if (tid < Nn) {
            int ci = sm->concepts[tid];
            unsigned long long cm = 0;
            for (int j = 0; j < Nn; j++)
                if (sm->concepts[j] == ci) cm |= 1ull << j;
            bool mi = (mb >> tid) & 1ull;
            unsigned long long e = mi ? (sm->adjraw[tid] & cm & mb) : 0ull;
            sm->reach[tid] = e | (1ull << tid);
        }
        __syncthreads();

        // ---- transitive closure by squaring (2^6 = 64 >= N) ----
        for (int it = 0; it < 6; it++) {
            unsigned long long r = 0;
            if (tid < Nn) {
                unsigned long long cur = sm->reach[tid];
                r = cur;
                unsigned long long t2 = cur;
                while (t2) {
                    int j = __ffsll((long long)t2) - 1;
                    r |= sm->reach[j];
                    t2 &= t2 - 1;
                }
            }
            __syncthreads();
            if (tid < Nn) sm->reach[tid] = r;
            __syncthreads();
        }

        // ---- roots -> present -> rank -> assignments ----
        if (tid == 0) { sm->present = 0ull; sm->ncl = 0; }
        if (tid < Nn) sm->nodemask[tid] = 0ull;
        __syncthreads();
        int root = 0;
        bool mi = false;
        if (tid < Nn) {
            mi = (mb >> tid) & 1ull;
            if (mi) {
                root = __ffsll((long long)sm->reach[tid]) - 1;
                atomicOr(&sm->present, 1ull << root);
            }
        }
        __syncthreads();
        if (tid < Nn) {
            int a = 0;
            if (mi) {
                unsigned long long pm =
                    sm->present & (0xFFFFFFFFFFFFFFFFull >> (63 - root));
                a = __popcll(pm);  // 1-based compact id
                atomicOr(&sm->nodemask[a - 1], 1ull << tid);
                atomicMax(&sm->ncl, a);
            }
            sm->assign[tid] = a;
            outAssign[(size_t)bs * Nn + tid] = (float)a;
        }
        __syncthreads();
        if (tid == 0) atomicMax(&g_maxcl[b], sm->ncl);

        // ---- cluster row-OR of raw adjacency ----
        if (tid < Nn) {
            unsigned long long nm = sm->nodemask[tid];
            unsigned long long ro = 0, t2 = nm;
            while (t2) {
                int j = __ffsll((long long)t2) - 1;
                ro |= sm->adjraw[j];
                t2 &= t2 - 1;
            }
            sm->rowOr[tid] = ro;
        }
        __syncthreads();

        // ---- cluster-adjacency counts + x_new sums ----
        if (tid < Nn) {
            if (sm->nodemask[tid]) {
                unsigned long long ro = sm->rowOr[tid];
                for (int c2 = 0; c2 < Nn; c2++)
                    if (ro & sm->nodemask[c2]) sm->adjc[tid * Nn + c2] += 1.f;
            }
        }
        if (tid < Hh) {
            int h = tid;
            for (int i2 = 0; i2 < Nn; i2++) {
                int ai = sm->assign[i2];
                if (ai > 0) sm->xnew[(ai - 1) * Hh + h] += sm->xa[h * PAD + i2];
            }
        }
        __syncthreads();
    }

    // ---- flush chunk accumulators (scaled by 1/S means) ----
    for (int idx = tid; idx < Nn * Hh; idx += 256) {
        float v = sm->xnew[idx];
        if (v != 0.f) atomicAdd(&outXnew[(size_t)b * Nn * Hh + idx], v * invS);
    }
    for (int idx = tid; idx < Nn * Nn; idx += 256) {
        float v = sm->adjc[idx];
        if (v != 0.f) atomicAdd(&outAdj[(size_t)b * Nn * Nn + idx], v * invS);
    }
}

// ---------------- kernel 4: mask_new ----------------
__global__ void finish_kernel(float* outMask) {
    int idx = blockIdx.x * blockDim.x + threadIdx.x;
    if (idx < Bq * Nn) {
        int b = idx / Nn, j = idx % Nn;
        outMask[idx] = (j < g_maxcl[b]) ? 1.f : 0.f;
    }
}

// ---------------- host launcher ----------------
extern "C" void kernel_launch(void* const* d_in, const int* in_sizes, int n_in,
                              void* d_out, int out_size) {
    const float* x   = (const float*)d_in[0];
    const float* adj = (const float*)d_in[1];
    const void*  msk = d_in[2];
    const float* W1  = (const float*)d_in[3];
    const float* b1  = (const float*)d_in[4];
    const float* W2  = (const float*)d_in[5];
    const float* b2  = (const float*)d_in[6];
    const float* cW1 = (const float*)d_in[7];
    const float* cb1 = (const float*)d_in[8];
    const float* cW2 = (const float*)d_in[9];
    const float* cb2 = (const float*)d_in[10];
    const float* noise = (const float*)d_in[11];

    int S = in_sizes[11] / in_sizes[0];  // (S*B*N*H) / (B*N*H)
    if (S <= 0) S = 1;

    float* out = (float*)d_out;
    size_t offAdj    = (size_t)Bq * Nn * Hh;
    size_t offAssign = offAdj + (size_t)Bq * Nn * Nn;
    size_t offXemb   = offAssign + (size_t)S * Bq * Nn;
    size_t offMask   = offXemb + (size_t)Bq * Nn * Hh;

    cudaFuncSetAttribute(main_kernel, cudaFuncAttributeMaxDynamicSharedMemorySize,
                         (int)sizeof(SmemK5));

    // 1) zero x_new + adj_new accumulator regions and g_maxcl
    zero_kernel<<<768, 256>>>(out, (int)offAssign);
    // 2) per-batch precompute
    prep_kernel<<<Bq, 64>>>(adj, msk);
    // 3) GCN layer 1 (x -> g_xe), layer 2 (g_xe -> x_emb output region)
    gcn_layer<<<Bq, 256>>>(x, W1, b1, nullptr, 0);
    gcn_layer<<<Bq, 256>>>(nullptr, W2, b2, out + offXemb, 1);
    // 4) main perturbed-clustering kernel
    int nchunk = (S + CHUNK - 1) / CHUNK;
    main_kernel<<<nchunk * Bq, 256, sizeof(SmemK5)>>>(
        out + offXemb, noise, cW1, cb1, cW2, cb2,
        out, out + offAdj, out + offAssign, S, 1.0f / (float)S);
    // 5) mask_new
    finish_kernel<<<(Bq * Nn + 255) / 256, 256>>>(out + offMask);
}

// round 2
// speedup vs baseline: 1.2424x; 1.2424x over previous
#include <cuda_runtime.h>
#include <cstdint>

#define Bq 32
#define Nn 64
#define Hh 128
#define Cc 16
#define SIGMA 0.5f
#define CHUNK 4
#define PAD 68

typedef unsigned long long ull;

// ---------------- f32x2 packed helpers (sm_103a) ----------------
__device__ __forceinline__ ull ffma2(ull a, ull b, ull c) {
    ull d;
    asm("fma.rn.f32x2 %0, %1, %2, %3;" : "=l"(d) : "l"(a), "l"(b), "l"(c));
    return d;
}
__device__ __forceinline__ ull pack2(float x, float y) {
    ull d;
    asm("mov.b64 %0, {%1, %2};" : "=l"(d) : "f"(x), "f"(y));
    return d;
}
__device__ __forceinline__ float lo2(ull v) { return __uint_as_float((unsigned)v); }
__device__ __forceinline__ float hi2(ull v) { return __uint_as_float((unsigned)(v >> 32)); }

// ---------------- device scratch (no allocation allowed) ----------------
__device__ float g_Anorm[Bq * Nn * Nn];
__device__ float g_xe[Bq * Nn * Hh];
__device__ float g_h[Bq * Nn * Hh];
__device__ unsigned long long g_adjbits[Bq * Nn];
__device__ unsigned long long g_maskbits[Bq];
__device__ int g_maxcl[Bq];

// ---------------- kernel 0: zero accumulators ----------------
__global__ void zero_kernel(float* out, int n) {
    for (int i = blockIdx.x * blockDim.x + threadIdx.x; i < n;
         i += gridDim.x * blockDim.x)
        out[i] = 0.f;
    if (blockIdx.x == 0 && threadIdx.x < Bq) g_maxcl[threadIdx.x] = 0;
}

// ---------------- kernel 1: per-batch precompute --------------
__global__ void prep_kernel(const float* __restrict__ adj, const void* maskp) {
    int b = blockIdx.x;
    int i = threadIdx.x;  // 64 threads
    __shared__ float deg[Nn];

    if (i == 0) {
        unsigned first = ((const unsigned*)maskp)[0];
        int mode = (first == 1u) ? 1 : ((first == 0x3F800000u) ? 2 : 0);
        unsigned long long bits = 0;
        for (int j = 0; j < Nn; j++) {
            bool m;
            if (mode == 0)      m = ((const unsigned char*)maskp)[b * Nn + j] != 0;
            else if (mode == 1) m = ((const int*)maskp)[b * Nn + j] != 0;
            else                m = ((const float*)maskp)[b * Nn + j] != 0.f;
            if (m) bits |= 1ull << j;
        }
        g_maskbits[b] = bits;
    }

    float s = 0.f;
    unsigned long long abits = 0;
    const float* arow = adj + (size_t)b * Nn * Nn + (size_t)i * Nn;
    for (int j = 0; j < Nn; j++) {
        float v = arow[j];
        if (v > 0.f) abits |= 1ull << j;
        s += (j == i) ? 1.f : v;
    }
    g_adjbits[b * Nn + i] = abits;
    deg[i] = rsqrtf(fmaxf(s, 1.f));
    __syncthreads();
    float di = deg[i];
    float* onorm = g_Anorm + (size_t)b * Nn * Nn + (size_t)i * Nn;
    for (int j = 0; j < Nn; j++) {
        float a = (j == i) ? 1.f : arow[j];
        onorm[j] = di * a * deg[j];
    }
}

// ---------------- kernel 2a: h = xin @ W ----------------------
// grid = Bq*4 (each block: 16 rows x 128 cols), 256 threads
__global__ __launch_bounds__(256) void gemm_xw(const float* __restrict__ xin_p,
                                               const float* __restrict__ W,
                                               int mode) {
    int b = blockIdx.x >> 2;
    int r0 = (blockIdx.x & 3) * 16;
    const float* xin = (mode == 0) ? xin_p : (const float*)g_xe;
    __shared__ float xs[16 * 128];  // rows r0..r0+16
    int tid = threadIdx.x;
    for (int idx = tid; idx < 16 * 128; idx += 256)
        xs[idx] = xin[((size_t)b * Nn + r0) * Hh + idx];
    __syncthreads();
    int ho = tid & 127, rg = tid >> 7;  // rg in {0,1}: rows rg*8..+8
    float acc[8];
#pragma unroll
    for (int q = 0; q < 8; q++) acc[q] = 0.f;
#pragma unroll 4
    for (int k = 0; k < Hh; k++) {
        float w = W[k * Hh + ho];
#pragma unroll
        for (int q = 0; q < 8; q++) acc[q] += xs[(rg * 8 + q) * 128 + k] * w;
    }
#pragma unroll
    for (int q = 0; q < 8; q++)
        g_h[((size_t)b * Nn + r0 + rg * 8 + q) * Hh + ho] = acc[q];
}

// ---------------- kernel 2b: out = relu(A@h + bias) * mask ----
// grid = Bq*2 (each block: 32 rows), 256 threads
__global__ __launch_bounds__(256) void gcn_agg(const float* __restrict__ bias,
                                               float* __restrict__ out_p,
                                               int mode) {
    int b = blockIdx.x >> 1;
    int r0 = (blockIdx.x & 1) * 32;
    __shared__ float hs[64 * 128];  // 32KB
    __shared__ float at[64 * 36];   // A transposed: at[j*36 + il]
    int tid = threadIdx.x;
    for (int idx = tid; idx < 64 * 128; idx += 256)
        hs[idx] = g_h[(size_t)b * Nn * Hh + idx];
    for (int idx = tid; idx < 32 * 64; idx += 256) {
        int il = idx >> 6, j = idx & 63;
        at[j * 36 + il] = g_Anorm[((size_t)b * Nn + r0 + il) * Nn + j];
    }
    __syncthreads();
    int ho = tid & 127, half = tid >> 7;
    int i0 = half * 16;
    float bv = bias[ho];
    float acc[16];
#pragma unroll
    for (int q = 0; q < 16; q++) acc[q] = bv;
#pragma unroll 2
    for (int j = 0; j < Nn; j++) {
        float hv = hs[j * 128 + ho];
        const float4* ar = (const float4*)(at + j * 36 + i0);
#pragma unroll
        for (int q = 0; q < 4; q++) {
            float4 v = ar[q];
            acc[q * 4 + 0] += v.x * hv;
            acc[q * 4 + 1] += v.y * hv;
            acc[q * 4 + 2] += v.z * hv;
            acc[q * 4 + 3] += v.w * hv;
        }
    }
    unsigned long long mb = g_maskbits[b];
    float* out = (mode == 0) ? (float*)g_xe : out_p;
#pragma unroll
    for (int q = 0; q < 16; q++) {
        int i = r0 + i0 + q;
        float v = ((mb >> i) & 1ull) ? fmaxf(acc[q], 0.f) : 0.f;
        out[((size_t)b * Nn + i) * Hh + ho] = v;
    }
}

// ---------------- kernel 3: main perturbed clustering ----------
struct SmemK5 {
    float xa[Hh * PAD];   // x_all transposed [h][node]
    float tt[Hh * PAD];   // relu(x@cW1+cb1) transposed [h][node]
    float xnew[Nn * Hh];  // per-chunk cluster sums
    float adjc[Nn * Nn];  // per-chunk cluster-adjacency counts
    float cw2[Hh * Cc];
    float lg[Nn * Cc];
    unsigned long long adjraw[Nn];
    unsigned long long reach[Nn];
    unsigned long long nodemask[Nn];
    unsigned long long rowOr[Nn];
    unsigned long long present;
    int concepts[Nn];
    int assign[Nn];
    int ncl;
};

__global__ __launch_bounds__(256) void main_kernel(
    const float* __restrict__ xemb, const float* __restrict__ noise,
    const float* __restrict__ cW1, const float* __restrict__ cb1,
    const float* __restrict__ cW2, const float* __restrict__ cb2,
    float* __restrict__ outXnew, float* __restrict__ outAdj,
    float* __restrict__ outAssign, int S, float invS) {
    extern __shared__ char smemraw[];
    SmemK5* sm = (SmemK5*)smemraw;
    int tid = threadIdx.x;  // 256
    int b = blockIdx.x % Bq;
    int chunk = blockIdx.x / Bq;

    for (int idx = tid; idx < Nn * Hh; idx += 256) sm->xnew[idx] = 0.f;
    for (int idx = tid; idx < Nn * Nn; idx += 256) sm->adjc[idx] = 0.f;
    for (int idx = tid; idx < Hh * Cc; idx += 256) sm->cw2[idx] = cW2[idx];
    if (tid < Nn) sm->adjraw[tid] = g_adjbits[b * Nn + tid];
    unsigned long long mb = g_maskbits[b];
    __syncthreads();

    int ho = tid & 127;
    int half = tid >> 7;
    float cb1v = cb1[ho];

    for (int sl = 0; sl < CHUNK; sl++) {
        int s = chunk * CHUNK + sl;
        if (s >= S) break;
        int bs = s * Bq + b;

        // ---- load x_all = x_emb + sigma*noise, transposed ----
        const float* xb = xemb + (size_t)b * Nn * Hh;
        const float* nz = noise + (size_t)bs * Nn * Hh;
        for (int idx = tid; idx < Nn * Hh; idx += 256) {
            int i = idx >> 7, h = idx & 127;
            sm->xa[h * PAD + i] = xb[idx] + SIGMA * nz[idx];
        }
        __syncthreads();

        // ---- t = relu(x_all @ cW1 + cb1), stored transposed (FFMA2) ----
        for (int g = 0; g < 2; g++) {
            int r0 = half * 32 + g * 16;
            ull acc2[8];
            ull binit = pack2(cb1v, cb1v);
#pragma unroll
            for (int p = 0; p < 8; p++) acc2[p] = binit;
#pragma unroll 4
            for (int k = 0; k < Hh; k++) {
                float w = cW1[k * Hh + ho];
                ull ww = pack2(w, w);
                const ulonglong2* xr = (const ulonglong2*)(sm->xa + k * PAD + r0);
#pragma unroll
                for (int q = 0; q < 2; q++) {
                    ulonglong2 p0 = xr[q * 2 + 0];
                    ulonglong2 p1 = xr[q * 2 + 1];
                    acc2[q * 4 + 0] = ffma2(p0.x, ww, acc2[q * 4 + 0]);
                    acc2[q * 4 + 1] = ffma2(p0.y, ww, acc2[q * 4 + 1]);
                    acc2[q * 4 + 2] = ffma2(p1.x, ww, acc2[q * 4 + 2]);
                    acc2[q * 4 + 3] = ffma2(p1.y, ww, acc2[q * 4 + 3]);
                }
            }
            float4* to = (float4*)(sm->tt + ho * PAD + r0);
#pragma unroll
            for (int q = 0; q < 4; q++) {
                float4 v;
                v.x = fmaxf(lo2(acc2[q * 2 + 0]), 0.f);
                v.y = fmaxf(hi2(acc2[q * 2 + 0]), 0.f);
                v.z = fmaxf(lo2(acc2[q * 2 + 1]), 0.f);
                v.w = fmaxf(hi2(acc2[q * 2 + 1]), 0.f);
                to[q] = v;
            }
        }
        __syncthreads();

        // ---- logits = t @ cW2 + cb2 (FFMA2) ----
        {
            int i = tid & 63, cg = tid >> 6;  // 4 cols per thread
            ull a01 = pack2(cb2[cg * 4 + 0], cb2[cg * 4 + 1]);
            ull a23 = pack2(cb2[cg * 4 + 2], cb2[cg * 4 + 3]);
#pragma unroll 4
            for (int k = 0; k < Hh; k++) {
                float tv = sm->tt[k * PAD + i];
                ull tvv = pack2(tv, tv);
                const ulonglong2* cr =
                    (const ulonglong2*)(sm->cw2 + k * Cc + cg * 4);
                ulonglong2 cv = cr[0];
                a01 = ffma2(tvv, cv.x, a01);
                a23 = ffma2(tvv, cv.y, a23);
            }
            sm->lg[i * Cc + cg * 4 + 0] = lo2(a01);
            sm->lg[i * Cc + cg * 4 + 1] = hi2(a01);
            sm->lg[i * Cc + cg * 4 + 2] = lo2(a23);
            sm->lg[i * Cc + cg * 4 + 3] = hi2(a23);
        }
        __syncthreads();

        // ---- argmax (first max, like jnp.argmax) ----
        if (tid < Nn) {
            float best = sm->lg[tid * Cc];
            int bi = 0;
            for (int c = 1; c < Cc; c++) {
                float v = sm->lg[tid * Cc + c];
                if (v > best) { best = v; bi = c; }
            }
            sm->concepts[tid] = bi;
        }
        __syncthreads();

        // ---- edges (same concept & masked) + reach init ----
        if (tid < Nn) {
            int ci = sm->concepts[tid];
            unsigned long long cm = 0;
            for (int j = 0; j < Nn; j++)
                if (sm->concepts[j] == ci) cm |= 1ull << j;
            bool mi = (mb >> tid) & 1ull;
            unsigned long long e = mi ? (sm->adjraw[tid] & cm & mb) : 0ull;
            sm->reach[tid] = e | (1ull << tid);
        }
        __syncthreads();

        // ---- transitive closure by squaring (2^6 = 64 >= N) ----
        for (int it = 0; it < 6; it++) {
            unsigned long long r = 0;
            if (tid < Nn) {
                unsigned long long cur = sm->reach[tid];
                r = cur;
                unsigned long long t2 = cur;
                while (t2) {
                    int j = __ffsll((long long)t2) - 1;
                    r |= sm->reach[j];
                    t2 &= t2 - 1;
                }
            }
            __syncthreads();
            if (tid < Nn) sm->reach[tid] = r;
            __syncthreads();
        }

        // ---- roots -> present -> rank -> assignments ----
        if (tid == 0) { sm->present = 0ull; sm->ncl = 0; }
        if (tid < Nn) sm->nodemask[tid] = 0ull;
        __syncthreads();
        int root = 0;
        bool mi = false;
        if (tid < Nn) {
            mi = (mb >> tid) & 1ull;
            if (mi) {
                root = __ffsll((long long)sm->reach[tid]) - 1;
                atomicOr(&sm->present, 1ull << root);
            }
        }
        __syncthreads();
        if (tid < Nn) {
            int a = 0;
            if (mi) {
                unsigned long long pm =
                    sm->present & (0xFFFFFFFFFFFFFFFFull >> (63 - root));
                a = __popcll(pm);  // 1-based compact id
                atomicOr(&sm->nodemask[a - 1], 1ull << tid);
                atomicMax(&sm->ncl, a);
            }
            sm->assign[tid] = a;
            outAssign[(size_t)bs * Nn + tid] = (float)a;
        }
        __syncthreads();
        if (tid == 0) atomicMax(&g_maxcl[b], sm->ncl);

        // ---- cluster row-OR of raw adjacency ----
        if (tid < Nn) {
            unsigned long long nm = sm->nodemask[tid];
            unsigned long long ro = 0, t2 = nm;
            while (t2) {
                int j = __ffsll((long long)t2) - 1;
                ro |= sm->adjraw[j];
                t2 &= t2 - 1;
            }
            sm->rowOr[tid] = ro;
        }
        __syncthreads();

        // ---- cluster-adjacency counts + x_new sums ----
        if (tid < Nn) {
            if (sm->nodemask[tid]) {
                unsigned long long ro = sm->rowOr[tid];
                for (int c2 = 0; c2 < Nn; c2++)
                    if (ro & sm->nodemask[c2]) sm->adjc[tid * Nn + c2] += 1.f;
            }
        }
        if (tid < Hh) {
            int h = tid;
            for (int i2 = 0; i2 < Nn; i2++) {
                int ai = sm->assign[i2];
                if (ai > 0) sm->xnew[(ai - 1) * Hh + h] += sm->xa[h * PAD + i2];
            }
        }
        __syncthreads();
    }

    // ---- flush chunk accumulators (scaled by 1/S means) ----
    for (int idx = tid; idx < Nn * Hh; idx += 256) {
        float v = sm->xnew[idx];
        if (v != 0.f) atomicAdd(&outXnew[(size_t)b * Nn * Hh + idx], v * invS);
    }
    for (int idx = tid; idx < Nn * Nn; idx += 256) {
        float v = sm->adjc[idx];
        if (v != 0.f) atomicAdd(&outAdj[(size_t)b * Nn * Nn + idx], v * invS);
    }
}

// ---------------- kernel 4: mask_new ----------------
__global__ void finish_kernel(float* outMask) {
    int idx = blockIdx.x * blockDim.x + threadIdx.x;
    if (idx < Bq * Nn) {
        int b = idx / Nn, j = idx % Nn;
        outMask[idx] = (j < g_maxcl[b]) ? 1.f : 0.f;
    }
}

// ---------------- host launcher ----------------
extern "C" void kernel_launch(void* const* d_in, const int* in_sizes, int n_in,
                              void* d_out, int out_size) {
    const float* x   = (const float*)d_in[0];
    const float* adj = (const float*)d_in[1];
    const void*  msk = d_in[2];
    const float* W1  = (const float*)d_in[3];
    const float* b1  = (const float*)d_in[4];
    const float* W2  = (const float*)d_in[5];
    const float* b2  = (const float*)d_in[6];
    const float* cW1 = (const float*)d_in[7];
    const float* cb1 = (const float*)d_in[8];
    const float* cW2 = (const float*)d_in[9];
    const float* cb2 = (const float*)d_in[10];
    const float* noise = (const float*)d_in[11];

    int S = in_sizes[11] / in_sizes[0];  // (S*B*N*H) / (B*N*H)
    if (S <= 0) S = 1;

    float* out = (float*)d_out;
    size_t offAdj    = (size_t)Bq * Nn * Hh;
    size_t offAssign = offAdj + (size_t)Bq * Nn * Nn;
    size_t offXemb   = offAssign + (size_t)S * Bq * Nn;
    size_t offMask   = offXemb + (size_t)Bq * Nn * Hh;

    cudaFuncSetAttribute(main_kernel, cudaFuncAttributeMaxDynamicSharedMemorySize,
                         (int)sizeof(SmemK5));

    // 1) zero x_new + adj_new accumulator regions and g_maxcl
    zero_kernel<<<768, 256>>>(out, (int)offAssign);
    // 2) per-batch precompute
    prep_kernel<<<Bq, 64>>>(adj, msk);
    // 3) GCN: layer1 = relu(A @ (x@W1) + b1)*mask -> g_xe
    gemm_xw<<<Bq * 4, 256>>>(x, W1, 0);
    gcn_agg<<<Bq * 2, 256>>>(b1, nullptr, 0);
    //    layer2 -> x_emb output region
    gemm_xw<<<Bq * 4, 256>>>(nullptr, W2, 1);
    gcn_agg<<<Bq * 2, 256>>>(b2, out + offXemb, 1);
    // 4) main perturbed-clustering kernel
    int nchunk = (S + CHUNK - 1) / CHUNK;
    main_kernel<<<nchunk * Bq, 256, sizeof(SmemK5)>>>(
        out + offXemb, noise, cW1, cb1, cW2, cb2,
        out, out + offAdj, out + offAssign, S, 1.0f / (float)S);
    // 5) mask_new
    finish_kernel<<<(Bq * Nn + 255) / 256, 256>>>(out + offMask);
}

// round 3
// speedup vs baseline: 1.8846x; 1.5169x over previous
#include <cuda_runtime.h>
#include <cstdint>

#define Bq 32
#define Nn 64
#define Hh 128
#define Cc 16
#define SIGMA 0.5f
#define CHUNK 4
#define PAD 68

typedef unsigned long long ull;

// ---------------- f32x2 packed helpers (sm_103a) ----------------
__device__ __forceinline__ ull ffma2(ull a, ull b, ull c) {
    ull d;
    asm("fma.rn.f32x2 %0, %1, %2, %3;" : "=l"(d) : "l"(a), "l"(b), "l"(c));
    return d;
}
__device__ __forceinline__ ull pack2(float x, float y) {
    ull d;
    asm("mov.b64 %0, {%1, %2};" : "=l"(d) : "f"(x), "f"(y));
    return d;
}
__device__ __forceinline__ float lo2(ull v) { return __uint_as_float((unsigned)v); }
__device__ __forceinline__ float hi2(ull v) { return __uint_as_float((unsigned)(v >> 32)); }

// ---------------- device scratch (no allocation allowed) ----------------
__device__ float g_Anorm[Bq * Nn * Nn];
__device__ float g_xe[Bq * Nn * Hh];
__device__ float g_h[Bq * Nn * Hh];
__device__ unsigned long long g_adjbits[Bq * Nn];
__device__ unsigned long long g_maskbits[Bq];
__device__ int g_maxcl[Bq];

// ---------------- kernel 1: zero accumulators + per-batch precompute ----
// (zeroing folded in so main_kernel is launch #6 for the ncu capture)
__global__ void prep_kernel(const float* __restrict__ adj, const void* maskp,
                            float* __restrict__ outZero, int nzero) {
    int b = blockIdx.x;
    int i = threadIdx.x;  // 64 threads
    __shared__ float deg[Nn];

    // zero x_new + adj_new accumulator regions (grid-stride over 32x64 threads)
    for (int idx = b * Nn + i; idx < nzero; idx += Bq * Nn) outZero[idx] = 0.f;
    if (b == 0 && i < Bq) g_maxcl[i] = 0;

    if (i == 0) {
        unsigned first = ((const unsigned*)maskp)[0];
        int mode = (first == 1u) ? 1 : ((first == 0x3F800000u) ? 2 : 0);
        unsigned long long bits = 0;
        for (int j = 0; j < Nn; j++) {
            bool m;
            if (mode == 0)      m = ((const unsigned char*)maskp)[b * Nn + j] != 0;
            else if (mode == 1) m = ((const int*)maskp)[b * Nn + j] != 0;
            else                m = ((const float*)maskp)[b * Nn + j] != 0.f;
            if (m) bits |= 1ull << j;
        }
        g_maskbits[b] = bits;
    }

    float s = 0.f;
    unsigned long long abits = 0;
    const float* arow = adj + (size_t)b * Nn * Nn + (size_t)i * Nn;
    for (int j = 0; j < Nn; j++) {
        float v = arow[j];
        if (v > 0.f) abits |= 1ull << j;
        s += (j == i) ? 1.f : v;
    }
    g_adjbits[b * Nn + i] = abits;
    deg[i] = rsqrtf(fmaxf(s, 1.f));
    __syncthreads();
    float di = deg[i];
    float* onorm = g_Anorm + (size_t)b * Nn * Nn + (size_t)i * Nn;
    for (int j = 0; j < Nn; j++) {
        float a = (j == i) ? 1.f : arow[j];
        onorm[j] = di * a * deg[j];
    }
}

// ---------------- kernel 2a: h = xin @ W ----------------------
__global__ __launch_bounds__(256) void gemm_xw(const float* __restrict__ xin_p,
                                               const float* __restrict__ W,
                                               int mode) {
    int b = blockIdx.x >> 2;
    int r0 = (blockIdx.x & 3) * 16;
    const float* xin = (mode == 0) ? xin_p : (const float*)g_xe;
    __shared__ float xs[16 * 128];
    int tid = threadIdx.x;
    for (int idx = tid; idx < 16 * 128; idx += 256)
        xs[idx] = xin[((size_t)b * Nn + r0) * Hh + idx];
    __syncthreads();
    int ho = tid & 127, rg = tid >> 7;
    float acc[8];
#pragma unroll
    for (int q = 0; q < 8; q++) acc[q] = 0.f;
#pragma unroll 4
    for (int k = 0; k < Hh; k++) {
        float w = W[k * Hh + ho];
#pragma unroll
        for (int q = 0; q < 8; q++) acc[q] += xs[(rg * 8 + q) * 128 + k] * w;
    }
#pragma unroll
    for (int q = 0; q < 8; q++)
        g_h[((size_t)b * Nn + r0 + rg * 8 + q) * Hh + ho] = acc[q];
}

// ---------------- kernel 2b: out = relu(A@h + bias) * mask ----
__global__ __launch_bounds__(256) void gcn_agg(const float* __restrict__ bias,
                                               float* __restrict__ out_p,
                                               int mode) {
    int b = blockIdx.x >> 1;
    int r0 = (blockIdx.x & 1) * 32;
    __shared__ float hs[64 * 128];
    __shared__ float at[64 * 36];
    int tid = threadIdx.x;
    for (int idx = tid; idx < 64 * 128; idx += 256)
        hs[idx] = g_h[(size_t)b * Nn * Hh + idx];
    for (int idx = tid; idx < 32 * 64; idx += 256) {
        int il = idx >> 6, j = idx & 63;
        at[j * 36 + il] = g_Anorm[((size_t)b * Nn + r0 + il) * Nn + j];
    }
    __syncthreads();
    int ho = tid & 127, half = tid >> 7;
    int i0 = half * 16;
    float bv = bias[ho];
    float acc[16];
#pragma unroll
    for (int q = 0; q < 16; q++) acc[q] = bv;
#pragma unroll 2
    for (int j = 0; j < Nn; j++) {
        float hv = hs[j * 128 + ho];
        const float4* ar = (const float4*)(at + j * 36 + i0);
#pragma unroll
        for (int q = 0; q < 4; q++) {
            float4 v = ar[q];
            acc[q * 4 + 0] += v.x * hv;
            acc[q * 4 + 1] += v.y * hv;
            acc[q * 4 + 2] += v.z * hv;
            acc[q * 4 + 3] += v.w * hv;
        }
    }
    unsigned long long mb = g_maskbits[b];
    float* out = (mode == 0) ? (float*)g_xe : out_p;
#pragma unroll
    for (int q = 0; q < 16; q++) {
        int i = r0 + i0 + q;
        float v = ((mb >> i) & 1ull) ? fmaxf(acc[q], 0.f) : 0.f;
        out[((size_t)b * Nn + i) * Hh + ho] = v;
    }
}

// ---------------- kernel 3: main perturbed clustering ----------
// smem cut to ~109KB -> 2 blocks/SM (16 warps). adjc + cW2 evicted to global.
struct SmemK5 {
    float xa[Hh * PAD];   // x_all transposed [h][node]   34816B
    float tt[Hh * PAD];   // relu(x@cW1+cb1) transposed   34816B
    float xnew[Nn * Hh];  // per-chunk cluster sums       32768B
    float lg[Nn * Cc];    //                              4096B
    unsigned long long adjraw[Nn];
    unsigned long long reach[Nn];
    unsigned long long nodemask[Nn];
    unsigned long long rowOr[Nn];
    unsigned long long present;
    int concepts[Nn];
    int assign[Nn];
    int ncl;
};

__global__ __launch_bounds__(256, 2) void main_kernel(
    const float* __restrict__ xemb, const float* __restrict__ noise,
    const float* __restrict__ cW1, const float* __restrict__ cb1,
    const float* __restrict__ cW2, const float* __restrict__ cb2,
    float* __restrict__ outXnew, float* __restrict__ outAdj,
    float* __restrict__ outAssign, int S, float invS) {
    extern __shared__ char smemraw[];
    SmemK5* sm = (SmemK5*)smemraw;
    int tid = threadIdx.x;  // 256
    int b = blockIdx.x % Bq;
    int chunk = blockIdx.x / Bq;

    for (int idx = tid; idx < Nn * Hh; idx += 256) sm->xnew[idx] = 0.f;
    if (tid < Nn) sm->adjraw[tid] = g_adjbits[b * Nn + tid];
    unsigned long long mb = g_maskbits[b];
    __syncthreads();

    int ho = tid & 127;
    int half = tid >> 7;
    int r0 = half * 32;
    float cb1v = cb1[ho];

    for (int sl = 0; sl < CHUNK; sl++) {
        int s = chunk * CHUNK + sl;
        if (s >= S) break;
        int bs = s * Bq + b;

        // ---- load x_all = x_emb + sigma*noise, transposed ----
        const float* xb = xemb + (size_t)b * Nn * Hh;
        const float* nz = noise + (size_t)bs * Nn * Hh;
#pragma unroll 8
        for (int idx = tid; idx < Nn * Hh; idx += 256) {
            int i = idx >> 7, h = idx & 127;
            sm->xa[h * PAD + i] = xb[idx] + SIGMA * nz[idx];
        }
        __syncthreads();

        // ---- t = relu(x_all @ cW1 + cb1), transposed (FFMA2, 32 nodes/thr) --
        {
            ull acc2[16];
            ull binit = pack2(cb1v, cb1v);
#pragma unroll
            for (int p = 0; p < 16; p++) acc2[p] = binit;
#pragma unroll 4
            for (int k = 0; k < Hh; k++) {
                float w = cW1[k * Hh + ho];
                ull ww = pack2(w, w);
                const ulonglong2* xr = (const ulonglong2*)(sm->xa + k * PAD + r0);
#pragma unroll
                for (int q = 0; q < 8; q++) {
                    ulonglong2 p0 = xr[q];
                    acc2[q * 2 + 0] = ffma2(p0.x, ww, acc2[q * 2 + 0]);
                    acc2[q * 2 + 1] = ffma2(p0.y, ww, acc2[q * 2 + 1]);
                }
            }
            float4* to = (float4*)(sm->tt + ho * PAD + r0);
#pragma unroll
            for (int q = 0; q < 8; q++) {
                float4 v;
                v.x = fmaxf(lo2(acc2[q * 2 + 0]), 0.f);
                v.y = fmaxf(hi2(acc2[q * 2 + 0]), 0.f);
                v.z = fmaxf(lo2(acc2[q * 2 + 1]), 0.f);
                v.w = fmaxf(hi2(acc2[q * 2 + 1]), 0.f);
                to[q] = v;
            }
        }
        __syncthreads();

        // ---- logits = t @ cW2 + cb2 (FFMA2, cW2 from L1) ----
        {
            int i = tid & 63, cg = tid >> 6;  // 4 cols per thread
            ull a01 = pack2(cb2[cg * 4 + 0], cb2[cg * 4 + 1]);
            ull a23 = pack2(cb2[cg * 4 + 2], cb2[cg * 4 + 3]);
#pragma unroll 4
            for (int k = 0; k < Hh; k++) {
                float tv = sm->tt[k * PAD + i];
                ull tvv = pack2(tv, tv);
                ulonglong2 cv = ((const ulonglong2*)(cW2 + k * Cc + cg * 4))[0];
                a01 = ffma2(tvv, cv.x, a01);
                a23 = ffma2(tvv, cv.y, a23);
            }
            sm->lg[i * Cc + cg * 4 + 0] = lo2(a01);
            sm->lg[i * Cc + cg * 4 + 1] = hi2(a01);
            sm->lg[i * Cc + cg * 4 + 2] = lo2(a23);
            sm->lg[i * Cc + cg * 4 + 3] = hi2(a23);
        }
        __syncthreads();

        // ---- argmax (first max, like jnp.argmax) ----
        if (tid < Nn) {
            float best = sm->lg[tid * Cc];
            int bi = 0;
            for (int c = 1; c < Cc; c++) {
                float v = sm->lg[tid * Cc + c];
                if (v > best) { best = v; bi = c; }
            }
            sm->concepts[tid] = bi;
        }
        __syncthreads();

        // ---- edges (same concept & masked) + reach init ----
        if (tid < Nn) {
            int ci = sm->concepts[tid];
            unsigned long long cm = 0;
            for (int j = 0; j < Nn; j++)
                if (sm->concepts[j] == ci) cm |= 1ull << j;
            bool mi = (mb >> tid) & 1ull;
            unsigned long long e = mi ? (sm->adjraw[tid] & cm & mb) : 0ull;
            sm->reach[tid] = e | (1ull << tid);
        }
        __syncthreads();

        // ---- transitive closure by squaring (2^6 = 64 >= N) ----
        for (int it = 0; it < 6; it++) {
            unsigned long long r = 0;
            if (tid < Nn) {
                unsigned long long cur = sm->reach[tid];
                r = cur;
                unsigned long long t2 = cur;
                while (t2) {
                    int j = __ffsll((long long)t2) - 1;
                    r |= sm->reach[j];
                    t2 &= t2 - 1;
                }
            }
            __syncthreads();
            if (tid < Nn) sm->reach[tid] = r;
            __syncthreads();
        }

        // ---- roots -> present -> rank -> assignments ----
        if (tid == 0) { sm->present = 0ull; sm->ncl = 0; }
        if (tid < Nn) sm->nodemask[tid] = 0ull;
        __syncthreads();
        int root = 0;
        bool mi = false;
        if (tid < Nn) {
            mi = (mb >> tid) & 1ull;
            if (mi) {
                root = __ffsll((long long)sm->reach[tid]) - 1;
                atomicOr(&sm->present, 1ull << root);
            }
        }
        __syncthreads();
        if (tid < Nn) {
            int a = 0;
            if (mi) {
                unsigned long long pm =
                    sm->present & (0xFFFFFFFFFFFFFFFFull >> (63 - root));
                a = __popcll(pm);  // 1-based compact id
                atomicOr(&sm->nodemask[a - 1], 1ull << tid);
                atomicMax(&sm->ncl, a);
            }
            sm->assign[tid] = a;
            outAssign[(size_t)bs * Nn + tid] = (float)a;
        }
        __syncthreads();
        if (tid == 0) atomicMax(&g_maxcl[b], sm->ncl);

        // ---- cluster row-OR of raw adjacency ----
        if (tid < Nn) {
            unsigned long long nm = sm->nodemask[tid];
            unsigned long long ro = 0, t2 = nm;
            while (t2) {
                int j = __ffsll((long long)t2) - 1;
                ro |= sm->adjraw[j];
                t2 &= t2 - 1;
            }
            sm->rowOr[tid] = ro;
        }
        __syncthreads();

        // ---- cluster-adjacency -> global atomics; x_new sums -> smem ----
        if (tid < Nn) {
            if (sm->nodemask[tid]) {
                unsigned long long ro = sm->rowOr[tid];
                float* arow = outAdj + (size_t)b * Nn * Nn + (size_t)tid * Nn;
                for (int c2 = 0; c2 < Nn; c2++)
                    if (ro & sm->nodemask[c2]) atomicAdd(&arow[c2], invS);
            }
        }
        if (tid < Hh) {
            int h = tid;
            for (int i2 = 0; i2 < Nn; i2++) {
                int ai = sm->assign[i2];
                if (ai > 0) sm->xnew[(ai - 1) * Hh + h] += sm->xa[h * PAD + i2];
            }
        }
        __syncthreads();
    }

    // ---- flush chunk x_new accumulator (scaled by 1/S means) ----
    for (int idx = tid; idx < Nn * Hh; idx += 256) {
        float v = sm->xnew[idx];
        if (v != 0.f) atomicAdd(&outXnew[(size_t)b * Nn * Hh + idx], v * invS);
    }
}

// ---------------- kernel 4: mask_new ----------------
__global__ void finish_kernel(float* outMask) {
    int idx = blockIdx.x * blockDim.x + threadIdx.x;
    if (idx < Bq * Nn) {
        int b = idx / Nn, j = idx % Nn;
        outMask[idx] = (j < g_maxcl[b]) ? 1.f : 0.f;
    }
}

// ---------------- host launcher ----------------
extern "C" void kernel_launch(void* const* d_in, const int* in_sizes, int n_in,
                              void* d_out, int out_size) {
    const float* x   = (const float*)d_in[0];
    const float* adj = (const float*)d_in[1];
    const void*  msk = d_in[2];
    const float* W1  = (const float*)d_in[3];
    const float* b1  = (const float*)d_in[4];
    const float* W2  = (const float*)d_in[5];
    const float* b2  = (const float*)d_in[6];
    const float* cW1 = (const float*)d_in[7];
    const float* cb1 = (const float*)d_in[8];
    const float* cW2 = (const float*)d_in[9];
    const float* cb2 = (const float*)d_in[10];
    const float* noise = (const float*)d_in[11];

    int S = in_sizes[11] / in_sizes[0];  // (S*B*N*H) / (B*N*H)
    if (S <= 0) S = 1;

    float* out = (float*)d_out;
    size_t offAdj    = (size_t)Bq * Nn * Hh;
    size_t offAssign = offAdj + (size_t)Bq * Nn * Nn;
    size_t offXemb   = offAssign + (size_t)S * Bq * Nn;
    size_t offMask   = offXemb + (size_t)Bq * Nn * Hh;

    cudaFuncSetAttribute(main_kernel, cudaFuncAttributeMaxDynamicSharedMemorySize,
                         (int)sizeof(SmemK5));

    // 1) zero accumulators + per-batch precompute (launch #1)
    prep_kernel<<<Bq, 64>>>(adj, msk, out, (int)offAssign);
    // 2) GCN: layer1 (launches #2,#3), layer2 (#4,#5)
    gemm_xw<<<Bq * 4, 256>>>(x, W1, 0);
    gcn_agg<<<Bq * 2, 256>>>(b1, nullptr, 0);
    gemm_xw<<<Bq * 4, 256>>>(nullptr, W2, 1);
    gcn_agg<<<Bq * 2, 256>>>(b2, out + offXemb, 1);
    // 3) main perturbed-clustering kernel (launch #6 -> ncu capture target)
    int nchunk = (S + CHUNK - 1) / CHUNK;
    main_kernel<<<nchunk * Bq, 256, sizeof(SmemK5)>>>(
        out + offXemb, noise, cW1, cb1, cW2, cb2,
        out, out + offAdj, out + offAssign, S, 1.0f / (float)S);
    // 4) mask_new
    finish_kernel<<<(Bq * Nn + 255) / 256, 256>>>(out + offMask);
}

// round 4
// speedup vs baseline: 2.0466x; 1.0860x over previous
#include <cuda_runtime.h>
#include <cstdint>

#define Bq 32
#define Nn 64
#define Hh 128
#define Cc 16
#define SIGMA 0.5f
#define PAD 68

typedef unsigned long long ull;

// ---------------- f32x2 packed helpers (sm_103a) ----------------
__device__ __forceinline__ ull ffma2(ull a, ull b, ull c) {
    ull d;
    asm("fma.rn.f32x2 %0, %1, %2, %3;" : "=l"(d) : "l"(a), "l"(b), "l"(c));
    return d;
}
__device__ __forceinline__ ull pack2(float x, float y) {
    ull d;
    asm("mov.b64 %0, {%1, %2};" : "=l"(d) : "f"(x), "f"(y));
    return d;
}
__device__ __forceinline__ float lo2(ull v) { return __uint_as_float((unsigned)v); }
__device__ __forceinline__ float hi2(ull v) { return __uint_as_float((unsigned)(v >> 32)); }

// ---------------- device scratch ----------------
__device__ float g_Anorm[Bq * Nn * Nn];
__device__ float g_h[Bq * Nn * Hh];
__device__ float g_h2[Bq * Nn * Hh];
__device__ unsigned long long g_adjbits[Bq * Nn];
__device__ unsigned long long g_maskbits[Bq];
__device__ int g_maxcl[Bq];

// ====== kernel 1: zero + prep + h1 = x @ W1  (32 blocks, 256 thr) ======
__global__ __launch_bounds__(256) void prep_gemm1(
    const float* __restrict__ x, const float* __restrict__ adj,
    const void* maskp, const float* __restrict__ W1,
    float* __restrict__ outZero, int nzero) {
    int b = blockIdx.x, tid = threadIdx.x;
    __shared__ float deg[Nn];
    __shared__ float xs[Hh * PAD];  // x transposed [h][node]

    // zero output accumulator regions (grid-stride, 8192 threads)
    for (int idx = b * 256 + tid; idx < nzero; idx += Bq * 256) outZero[idx] = 0.f;
    if (b == 0 && tid < Bq) g_maxcl[tid] = 0;

    if (tid == 0) {
        unsigned first = ((const unsigned*)maskp)[0];
        int mode = (first == 1u) ? 1 : ((first == 0x3F800000u) ? 2 : 0);
        unsigned long long bits = 0;
        for (int j = 0; j < Nn; j++) {
            bool m;
            if (mode == 0)      m = ((const unsigned char*)maskp)[b * Nn + j] != 0;
            else if (mode == 1) m = ((const int*)maskp)[b * Nn + j] != 0;
            else                m = ((const float*)maskp)[b * Nn + j] != 0.f;
            if (m) bits |= 1ull << j;
        }
        g_maskbits[b] = bits;
    }
    if (tid < Nn) {
        float s = 0.f;
        unsigned long long abits = 0;
        const float* arow = adj + (size_t)b * Nn * Nn + (size_t)tid * Nn;
        for (int j = 0; j < Nn; j++) {
            float v = arow[j];
            if (v > 0.f) abits |= 1ull << j;
            s += (j == tid) ? 1.f : v;
        }
        g_adjbits[b * Nn + tid] = abits;
        deg[tid] = rsqrtf(fmaxf(s, 1.f));
    }
    // stage x transposed
    for (int idx = tid; idx < Nn * Hh; idx += 256) {
        int i = idx >> 7, h = idx & 127;
        xs[h * PAD + i] = x[(size_t)b * Nn * Hh + idx];
    }
    __syncthreads();
    // Anorm
    for (int idx = tid; idx < Nn * Nn; idx += 256) {
        int i = idx >> 6, j = idx & 63;
        float a = (i == j) ? 1.f : adj[(size_t)b * Nn * Nn + idx];
        g_Anorm[(size_t)b * Nn * Nn + idx] = deg[i] * a * deg[j];
    }
    // h1 = x @ W1 : thread (ho, rg) covers 32 rows
    int ho = tid & 127, rg = tid >> 7, r0 = rg * 32;
    ull acc2[16];
#pragma unroll
    for (int p = 0; p < 16; p++) acc2[p] = 0ull;
#pragma unroll 4
    for (int k = 0; k < Hh; k++) {
        float w = W1[k * Hh + ho];
        ull ww = pack2(w, w);
        const ulonglong2* xr = (const ulonglong2*)(xs + k * PAD + r0);
#pragma unroll
        for (int q = 0; q < 8; q++) {
            ulonglong2 p0 = xr[q];
            acc2[q * 2 + 0] = ffma2(p0.x, ww, acc2[q * 2 + 0]);
            acc2[q * 2 + 1] = ffma2(p0.y, ww, acc2[q * 2 + 1]);
        }
    }
#pragma unroll
    for (int p = 0; p < 16; p++) {
        g_h[((size_t)b * Nn + r0 + 2 * p + 0) * Hh + ho] = lo2(acc2[p]);
        g_h[((size_t)b * Nn + r0 + 2 * p + 1) * Hh + ho] = hi2(acc2[p]);
    }
}

// ====== kernel 2: xe = relu(A@h1+b1)*mask fused with h2 = xe @ W2 ======
// 64 blocks (2 per batch: 32 rows each), 256 threads
__global__ __launch_bounds__(256) void agg1_gemm2(const float* __restrict__ b1,
                                                  const float* __restrict__ W2) {
    int b = blockIdx.x >> 1;
    int r0 = (blockIdx.x & 1) * 32;
    __shared__ float hs[Nn * Hh];    // 32KB h1 full batch
    __shared__ float at[Nn * 36];    // A^T tile
    __shared__ float xet[Hh * 36];   // xe rows r0..r0+32 transposed [k][row]
    int tid = threadIdx.x;
    for (int idx = tid; idx < Nn * Hh; idx += 256)
        hs[idx] = g_h[(size_t)b * Nn * Hh + idx];
    for (int idx = tid; idx < 32 * Nn; idx += 256) {
        int il = idx >> 6, j = idx & 63;
        at[j * 36 + il] = g_Anorm[((size_t)b * Nn + r0 + il) * Nn + j];
    }
    __syncthreads();
    int ho = tid & 127, half = tid >> 7;
    int i0 = half * 16;
    float bv = b1[ho];
    float acc[16];
#pragma unroll
    for (int q = 0; q < 16; q++) acc[q] = bv;
#pragma unroll 2
    for (int j = 0; j < Nn; j++) {
        float hv = hs[j * Hh + ho];
        const float4* ar = (const float4*)(at + j * 36 + i0);
#pragma unroll
        for (int q = 0; q < 4; q++) {
            float4 v = ar[q];
            acc[q * 4 + 0] += v.x * hv;
            acc[q * 4 + 1] += v.y * hv;
            acc[q * 4 + 2] += v.z * hv;
            acc[q * 4 + 3] += v.w * hv;
        }
    }
    unsigned long long mb = g_maskbits[b];
#pragma unroll
    for (int q = 0; q < 16; q++) {
        int i = r0 + i0 + q;
        float v = ((mb >> i) & 1ull) ? fmaxf(acc[q], 0.f) : 0.f;
        xet[ho * 36 + i0 + q] = v;
    }
    __syncthreads();
    // h2 = xe @ W2 for local rows half*16..+16
    ull acc2[8];
#pragma unroll
    for (int p = 0; p < 8; p++) acc2[p] = 0ull;
#pragma unroll 4
    for (int k = 0; k < Hh; k++) {
        float w = W2[k * Hh + ho];
        ull ww = pack2(w, w);
        const ulonglong2* xr = (const ulonglong2*)(xet + k * 36 + half * 16);
#pragma unroll
        for (int q = 0; q < 4; q++) {
            ulonglong2 p0 = xr[q];
            acc2[q * 2 + 0] = ffma2(p0.x, ww, acc2[q * 2 + 0]);
            acc2[q * 2 + 1] = ffma2(p0.y, ww, acc2[q * 2 + 1]);
        }
    }
#pragma unroll
    for (int p = 0; p < 8; p++) {
        g_h2[((size_t)b * Nn + r0 + half * 16 + 2 * p + 0) * Hh + ho] = lo2(acc2[p]);
        g_h2[((size_t)b * Nn + r0 + half * 16 + 2 * p + 1) * Hh + ho] = hi2(acc2[p]);
    }
}

// ====== kernel 3: x_emb = relu(A@h2 + b2)*mask ======
__global__ __launch_bounds__(256) void agg2(const float* __restrict__ bias,
                                            float* __restrict__ out_p) {
    int b = blockIdx.x >> 1;
    int r0 = (blockIdx.x & 1) * 32;
    __shared__ float hs[Nn * Hh];
    __shared__ float at[Nn * 36];
    int tid = threadIdx.x;
    for (int idx = tid; idx < Nn * Hh; idx += 256)
        hs[idx] = g_h2[(size_t)b * Nn * Hh + idx];
    for (int idx = tid; idx < 32 * Nn; idx += 256) {
        int il = idx >> 6, j = idx & 63;
        at[j * 36 + il] = g_Anorm[((size_t)b * Nn + r0 + il) * Nn + j];
    }
    __syncthreads();
    int ho = tid & 127, half = tid >> 7;
    int i0 = half * 16;
    float bv = bias[ho];
    float acc[16];
#pragma unroll
    for (int q = 0; q < 16; q++) acc[q] = bv;
#pragma unroll 2
    for (int j = 0; j < Nn; j++) {
        float hv = hs[j * Hh + ho];
        const float4* ar = (const float4*)(at + j * 36 + i0);
#pragma unroll
        for (int q = 0; q < 4; q++) {
            float4 v = ar[q];
            acc[q * 4 + 0] += v.x * hv;
            acc[q * 4 + 1] += v.y * hv;
            acc[q * 4 + 2] += v.z * hv;
            acc[q * 4 + 3] += v.w * hv;
        }
    }
    unsigned long long mb = g_maskbits[b];
#pragma unroll
    for (int q = 0; q < 16; q++) {
        int i = r0 + i0 + q;
        float v = ((mb >> i) & 1ull) ? fmaxf(acc[q], 0.f) : 0.f;
        out_p[((size_t)b * Nn + i) * Hh + ho] = v;
    }
}

// ====== kernel 4: main perturbed clustering (launch slot #4 for ncu) ======
struct SmemK5 {
    float xa[Hh * PAD];
    float tt[Hh * PAD];
    float xnew[Nn * Hh];
    float lg[Nn * Cc];
    unsigned long long adjraw[Nn];
    unsigned long long reach[Nn];
    unsigned long long nodemask[Nn];
    unsigned long long rowOr[Nn];
    unsigned long long present;
    int concepts[Nn];
    int assign[Nn];
    int ncl;
};

__global__ __launch_bounds__(256, 2) void main_kernel(
    const float* __restrict__ xemb, const float* __restrict__ noise,
    const float* __restrict__ cW1, const float* __restrict__ cb1,
    const float* __restrict__ cW2, const float* __restrict__ cb2,
    float* __restrict__ outXnew, float* __restrict__ outAdj,
    float* __restrict__ outAssign, int S, int NC, float invS) {
    extern __shared__ char smemraw[];
    SmemK5* sm = (SmemK5*)smemraw;
    int tid = threadIdx.x;
    int b = blockIdx.x % Bq;
    int chunk = blockIdx.x / Bq;

    for (int idx = tid; idx < Nn * Hh; idx += 256) sm->xnew[idx] = 0.f;
    if (tid < Nn) sm->adjraw[tid] = g_adjbits[b * Nn + tid];
    unsigned long long mb = g_maskbits[b];
    __syncthreads();

    int ho = tid & 127;
    int half = tid >> 7;
    int r0 = half * 32;
    float cb1v = cb1[ho];

    for (int s = chunk; s < S; s += NC) {
        int bs = s * Bq + b;

        // ---- load x_all = x_emb + sigma*noise, transposed ----
        const float* xb = xemb + (size_t)b * Nn * Hh;
        const float* nz = noise + (size_t)bs * Nn * Hh;
#pragma unroll 8
        for (int idx = tid; idx < Nn * Hh; idx += 256) {
            int i = idx >> 7, h = idx & 127;
            sm->xa[h * PAD + i] = xb[idx] + SIGMA * nz[idx];
        }
        __syncthreads();

        // ---- t = relu(x_all @ cW1 + cb1), transposed (FFMA2) ----
        {
            ull acc2[16];
            ull binit = pack2(cb1v, cb1v);
#pragma unroll
            for (int p = 0; p < 16; p++) acc2[p] = binit;
#pragma unroll 4
            for (int k = 0; k < Hh; k++) {
                float w = cW1[k * Hh + ho];
                ull ww = pack2(w, w);
                const ulonglong2* xr = (const ulonglong2*)(sm->xa + k * PAD + r0);
#pragma unroll
                for (int q = 0; q < 8; q++) {
                    ulonglong2 p0 = xr[q];
                    acc2[q * 2 + 0] = ffma2(p0.x, ww, acc2[q * 2 + 0]);
                    acc2[q * 2 + 1] = ffma2(p0.y, ww, acc2[q * 2 + 1]);
                }
            }
            float4* to = (float4*)(sm->tt + ho * PAD + r0);
#pragma unroll
            for (int q = 0; q < 8; q++) {
                float4 v;
                v.x = fmaxf(lo2(acc2[q * 2 + 0]), 0.f);
                v.y = fmaxf(hi2(acc2[q * 2 + 0]), 0.f);
                v.z = fmaxf(lo2(acc2[q * 2 + 1]), 0.f);
                v.w = fmaxf(hi2(acc2[q * 2 + 1]), 0.f);
                to[q] = v;
            }
        }
        __syncthreads();

        // ---- logits = t @ cW2 + cb2 (FFMA2, cW2 via L1) ----
        {
            int i = tid & 63, cg = tid >> 6;
            ull a01 = pack2(cb2[cg * 4 + 0], cb2[cg * 4 + 1]);
            ull a23 = pack2(cb2[cg * 4 + 2], cb2[cg * 4 + 3]);
#pragma unroll 4
            for (int k = 0; k < Hh; k++) {
                float tv = sm->tt[k * PAD + i];
                ull tvv = pack2(tv, tv);
                ulonglong2 cv = ((const ulonglong2*)(cW2 + k * Cc + cg * 4))[0];
                a01 = ffma2(tvv, cv.x, a01);
                a23 = ffma2(tvv, cv.y, a23);
            }
            sm->lg[i * Cc + cg * 4 + 0] = lo2(a01);
            sm->lg[i * Cc + cg * 4 + 1] = hi2(a01);
            sm->lg[i * Cc + cg * 4 + 2] = lo2(a23);
            sm->lg[i * Cc + cg * 4 + 3] = hi2(a23);
        }
        __syncthreads();

        // ---- argmax ----
        if (tid < Nn) {
            float best = sm->lg[tid * Cc];
            int bi = 0;
            for (int c = 1; c < Cc; c++) {
                float v = sm->lg[tid * Cc + c];
                if (v > best) { best = v; bi = c; }
            }
            sm->concepts[tid] = bi;
        }
        __syncthreads();

        // ---- edges + reach init ----
        if (tid < Nn) {
            int ci = sm->concepts[tid];
            unsigned long long cm = 0;
            for (int j = 0; j < Nn; j++)
                if (sm->concepts[j] == ci) cm |= 1ull << j;
            bool mi = (mb >> tid) & 1ull;
            unsigned long long e = mi ? (sm->adjraw[tid] & cm & mb) : 0ull;
            sm->reach[tid] = e | (1ull << tid);
        }
        __syncthreads();

        // ---- transitive closure by squaring ----
        for (int it = 0; it < 6; it++) {
            unsigned long long r = 0;
            if (tid < Nn) {
                unsigned long long cur = sm->reach[tid];
                r = cur;
                unsigned long long t2 = cur;
                while (t2) {
                    int j = __ffsll((long long)t2) - 1;
                    r |= sm->reach[j];
                    t2 &= t2 - 1;
                }
            }
            __syncthreads();
            if (tid < Nn) sm->reach[tid] = r;
            __syncthreads();
        }

        // ---- roots -> present -> rank -> assignments ----
        if (tid == 0) { sm->present = 0ull; sm->ncl = 0; }
        if (tid < Nn) sm->nodemask[tid] = 0ull;
        __syncthreads();
        int root = 0;
        bool mi = false;
        if (tid < Nn) {
            mi = (mb >> tid) & 1ull;
            if (mi) {
                root = __ffsll((long long)sm->reach[tid]) - 1;
                atomicOr(&sm->present, 1ull << root);
            }
        }
        __syncthreads();
        if (tid < Nn) {
            int a = 0;
            if (mi) {
                unsigned long long pm =
                    sm->present & (0xFFFFFFFFFFFFFFFFull >> (63 - root));
                a = __popcll(pm);
                atomicOr(&sm->nodemask[a - 1], 1ull << tid);
                atomicMax(&sm->ncl, a);
            }
            sm->assign[tid] = a;
            outAssign[(size_t)bs * Nn + tid] = (float)a;
        }
        __syncthreads();
        if (tid == 0) atomicMax(&g_maxcl[b], sm->ncl);

        // ---- cluster row-OR ----
        if (tid < Nn) {
            unsigned long long nm = sm->nodemask[tid];
            unsigned long long ro = 0, t2 = nm;
            while (t2) {
                int j = __ffsll((long long)t2) - 1;
                ro |= sm->adjraw[j];
                t2 &= t2 - 1;
            }
            sm->rowOr[tid] = ro;
        }
        __syncthreads();

        // ---- cluster-adjacency -> global atomics; x_new sums -> smem ----
        if (tid < Nn) {
            if (sm->nodemask[tid]) {
                unsigned long long ro = sm->rowOr[tid];
                float* arow = outAdj + (size_t)b * Nn * Nn + (size_t)tid * Nn;
                for (int c2 = 0; c2 < Nn; c2++)
                    if (ro & sm->nodemask[c2]) atomicAdd(&arow[c2], invS);
            }
        }
        if (tid < Hh) {
            int h = tid;
            for (int i2 = 0; i2 < Nn; i2++) {
                int ai = sm->assign[i2];
                if (ai > 0) sm->xnew[(ai - 1) * Hh + h] += sm->xa[h * PAD + i2];
            }
        }
        __syncthreads();
    }

    // ---- flush x_new accumulator ----
    for (int idx = tid; idx < Nn * Hh; idx += 256) {
        float v = sm->xnew[idx];
        if (v != 0.f) atomicAdd(&outXnew[(size_t)b * Nn * Hh + idx], v * invS);
    }
}

// ====== kernel 5: mask_new ======
__global__ void finish_kernel(float* outMask) {
    int idx = blockIdx.x * blockDim.x + threadIdx.x;
    if (idx < Bq * Nn) {
        int b = idx / Nn, j = idx % Nn;
        outMask[idx] = (j < g_maxcl[b]) ? 1.f : 0.f;
    }
}

// ---------------- host launcher ----------------
extern "C" void kernel_launch(void* const* d_in, const int* in_sizes, int n_in,
                              void* d_out, int out_size) {
    const float* x   = (const float*)d_in[0];
    const float* adj = (const float*)d_in[1];
    const void*  msk = d_in[2];
    const float* W1  = (const float*)d_in[3];
    const float* b1  = (const float*)d_in[4];
    const float* W2  = (const float*)d_in[5];
    const float* b2  = (const float*)d_in[6];
    const float* cW1 = (const float*)d_in[7];
    const float* cb1 = (const float*)d_in[8];
    const float* cW2 = (const float*)d_in[9];
    const float* cb2 = (const float*)d_in[10];
    const float* noise = (const float*)d_in[11];

    int S = in_sizes[11] / in_sizes[0];
    if (S <= 0) S = 1;

    float* out = (float*)d_out;
    size_t offAdj    = (size_t)Bq * Nn * Hh;
    size_t offAssign = offAdj + (size_t)Bq * Nn * Nn;
    size_t offXemb   = offAssign + (size_t)S * Bq * Nn;
    size_t offMask   = offXemb + (size_t)Bq * Nn * Hh;

    cudaFuncSetAttribute(main_kernel, cudaFuncAttributeMaxDynamicSharedMemorySize,
                         (int)sizeof(SmemK5));

    // #1: zero + prep + h1
    prep_gemm1<<<Bq, 256>>>(x, adj, msk, W1, out, (int)offAssign);
    // #2: xe + h2 (fused)
    agg1_gemm2<<<Bq * 2, 256>>>(b1, W2);
    // #3: x_emb
    agg2<<<Bq * 2, 256>>>(b2, out + offXemb);
    // #4: main (ncu capture slot)
    int NC = (S < 28) ? S : 28;  // ~3.03 waves at 2 blocks/SM on 148 SMs
    main_kernel<<<NC * Bq, 256, sizeof(SmemK5)>>>(
        out + offXemb, noise, cW1, cb1, cW2, cb2,
        out, out + offAdj, out + offAssign, S, NC, 1.0f / (float)S);
    // #5: mask_new
    finish_kernel<<<(Bq * Nn + 255) / 256, 256>>>(out + offMask);
}